// round 9
// baseline (speedup 1.0000x reference)
#include <cuda_runtime.h>
#include <cuda_bf16.h>
#include <cstdint>
#include <math.h>

// Fixed problem shapes
#define CC   192
#define NN   4096           // 16^3
#define HID  384
#define MLPH 768
#define NH   6
#define HD   32
#define QKV3 576

// ---------------- scratch ----------------------------------------------------
__device__ float g_stats[2 * CC];            // [0:192)=sum, [192:384)=sumsq
__device__ float g_mult[CC];
__device__ float g_xT[(size_t)NN * CC];      // x transposed (pos, chan)
__device__ float g_qkv[(size_t)NN * QKV3];   // (pos, 576)
__device__ float g_oatt[(size_t)NN * CC];    // (pos, chan)
__device__ float g_x2[(size_t)NN * CC];      // (pos, chan)
__device__ float g_m1[(size_t)NN * MLPH];    // (pos, 768)
__device__ float g_y[(size_t)NN * CC];       // (pos, chan)

// ---------------- helpers ----------------------------------------------------
__device__ __forceinline__ float warp_sum(float v) {
#pragma unroll
    for (int o = 16; o; o >>= 1) v += __shfl_xor_sync(0xffffffffu, v, o);
    return v;
}
__device__ __forceinline__ float warp_max(float v) {
#pragma unroll
    for (int o = 16; o; o >>= 1) v = fmaxf(v, __shfl_xor_sync(0xffffffffu, v, o));
    return v;
}
__device__ __forceinline__ uint32_t f2tf(float x) {
    uint32_t r;
    asm("cvt.rna.tf32.f32 %0, %1;" : "=r"(r) : "f"(x));
    return r;
}
__device__ __forceinline__ void mma_tf32(float* c, const uint32_t* a, const uint32_t* b) {
    asm volatile(
        "mma.sync.aligned.m16n8k8.row.col.f32.tf32.tf32.f32 "
        "{%0,%1,%2,%3}, {%4,%5,%6,%7}, {%8,%9}, {%0,%1,%2,%3};\n"
        : "+f"(c[0]), "+f"(c[1]), "+f"(c[2]), "+f"(c[3])
        : "r"(a[0]), "r"(a[1]), "r"(a[2]), "r"(a[3]), "r"(b[0]), "r"(b[1]));
}

// ---------------- fused transpose (C,N)->(N,C) + per-channel stats ------------
__global__ void transpose_stats(const float* __restrict__ in, float* __restrict__ outp,
                                float* __restrict__ stats) {
    __shared__ float tle[32][33];
    int c0 = blockIdx.x * 32;  // position block
    int r0 = blockIdx.y * 32;  // channel block
    int tx = threadIdx.x, ty = threadIdx.y;
#pragma unroll
    for (int u = 0; u < 32; u += 8)
        tle[ty + u][tx] = in[(size_t)(r0 + ty + u) * NN + c0 + tx];
    __syncthreads();
#pragma unroll
    for (int u = 0; u < 32; u += 8)
        outp[(size_t)(c0 + ty + u) * CC + r0 + tx] = tle[tx][ty + u];
    if (ty == 0) {
        float s = 0.f, s2 = 0.f;
#pragma unroll
        for (int p = 0; p < 32; p++) { float v = tle[tx][p]; s += v; s2 += v * v; }
        atomicAdd(&stats[r0 + tx], s);
        atomicAdd(&stats[CC + r0 + tx], s2);
    }
}

// ---------------- plain transpose (R,C) -> (C,R) ------------------------------
__global__ void transpose_k(const float* __restrict__ in, float* __restrict__ out,
                            int R, int C) {
    __shared__ float t[32][33];
    int c0 = blockIdx.x * 32, r0 = blockIdx.y * 32;
    int tx = threadIdx.x, ty = threadIdx.y;
#pragma unroll
    for (int u = 0; u < 32; u += 8)
        t[ty + u][tx] = in[(size_t)(r0 + ty + u) * C + c0 + tx];
    __syncthreads();
#pragma unroll
    for (int u = 0; u < 32; u += 8)
        out[(size_t)(c0 + ty + u) * R + r0 + tx] = t[tx][ty + u];
}

// ---------------- fused ada gating (hidden + mult + optional zero) ------------
__global__ void __launch_bounds__(512) ada_fused(
    float* __restrict__ stats,
    const float* __restrict__ w1, const float* __restrict__ b1,
    const float* __restrict__ w2, const float* __restrict__ b2,
    const float* __restrict__ scale, float* __restrict__ mult, int zero) {
    __shared__ float mean_s[CC];
    __shared__ float h_s[HID];
    int tid = threadIdx.x, wid = tid >> 5, lane = tid & 31;
    if (tid < CC) mean_s[tid] = stats[tid] * (1.f / NN);
    __syncthreads();
    for (int r = wid; r < HID; r += 16) {
        const float* wr = w1 + (size_t)r * CC;
        float a = 0.f;
#pragma unroll
        for (int c = lane; c < CC; c += 32) a += mean_s[c] * wr[c];
        a = warp_sum(a);
        if (lane == 0) h_s[r] = fmaxf(a + b1[r], 0.f);
    }
    __syncthreads();
    for (int r = wid; r < CC; r += 16) {
        const float* wr = w2 + (size_t)r * HID;
        float a = 0.f;
#pragma unroll
        for (int i = lane; i < HID; i += 32) a += h_s[i] * wr[i];
        a = warp_sum(a);
        if (lane == 0) {
            float g = 1.f / (1.f + __expf(-(a + b2[r])));
            mult[r] = scale[r] * g * rsqrtf(stats[CC + r] * (1.f / NN) + 1e-6f);
        }
    }
    if (zero) {
        __syncthreads();
        if (tid < 2 * CC) stats[tid] = 0.f;
    }
}

// ---------------- tf32 tensor-core GEMM ---------------------------------------
// out(M,N) = epi( A(M,K)*diag(Amult) @ B(N,K)^T + bias[col] )  [+residual] [stats]
// CTA tile 128x64x16, 8 warps of 32x32, mma.m16n8k8.tf32.
#define SA 20   // smem row stride (16 + 4 pad) -> conflict-free fragment loads

template <int GELU, int RES, int STATS>
__global__ void __launch_bounds__(256) gemm_tc(
    int M, int N, int K,
    const float* __restrict__ A, const float* __restrict__ Amult,
    const float* __restrict__ B,
    const float* __restrict__ bias,
    const float* __restrict__ residual,
    float* __restrict__ out,
    float* __restrict__ stats) {
    __shared__ uint32_t As[2][128 * SA];
    __shared__ uint32_t Bs[2][64 * SA];

    const int i0 = blockIdx.y * 128, j0 = blockIdx.x * 64;
    const int tid = threadIdx.x;
    const int rl = tid >> 2, fl = (tid & 3) * 4;
    const int warp = tid >> 5, lane = tid & 31;
    const int wm = warp >> 1, wn = warp & 1;
    const int gid = lane >> 2, tig = lane & 3;

    const float* Ap = A + (size_t)(i0 + rl) * K + fl;
    const float* Aq = A + (size_t)(i0 + rl + 64) * K + fl;
    const float* Bp = B + (size_t)(j0 + rl) * K + fl;

    // preload tile 0
    {
        float4 a0 = *(const float4*)Ap;
        float4 a1 = *(const float4*)Aq;
        float4 b0 = *(const float4*)Bp;
        float4 mm = Amult ? *(const float4*)(Amult + fl) : make_float4(1.f, 1.f, 1.f, 1.f);
        uint4 ua = make_uint4(f2tf(a0.x * mm.x), f2tf(a0.y * mm.y),
                              f2tf(a0.z * mm.z), f2tf(a0.w * mm.w));
        uint4 ub = make_uint4(f2tf(a1.x * mm.x), f2tf(a1.y * mm.y),
                              f2tf(a1.z * mm.z), f2tf(a1.w * mm.w));
        uint4 uc = make_uint4(f2tf(b0.x), f2tf(b0.y), f2tf(b0.z), f2tf(b0.w));
        *(uint4*)&As[0][rl * SA + fl] = ua;
        *(uint4*)&As[0][(rl + 64) * SA + fl] = ub;
        *(uint4*)&Bs[0][rl * SA + fl] = uc;
    }
    __syncthreads();

    float acc[2][4][4] = {};
    const int nk = K / 16;

    for (int t = 0; t < nk; t++) {
        const int buf = t & 1;
        float4 na0, na1, nb0, nmm;
        if (t + 1 < nk) {
            int off = (t + 1) * 16;
            na0 = *(const float4*)(Ap + off);
            na1 = *(const float4*)(Aq + off);
            nb0 = *(const float4*)(Bp + off);
            nmm = Amult ? *(const float4*)(Amult + off + fl) : make_float4(1.f, 1.f, 1.f, 1.f);
        }
#pragma unroll
        for (int kc = 0; kc < 16; kc += 8) {
            uint32_t af[2][4], bf[4][2];
#pragma unroll
            for (int mt = 0; mt < 2; mt++) {
                int r0 = (wm * 32 + mt * 16 + gid) * SA + kc + tig;
                af[mt][0] = As[buf][r0];
                af[mt][1] = As[buf][r0 + 8 * SA];
                af[mt][2] = As[buf][r0 + 4];
                af[mt][3] = As[buf][r0 + 8 * SA + 4];
            }
#pragma unroll
            for (int nt = 0; nt < 4; nt++) {
                int n0 = (wn * 32 + nt * 8 + gid) * SA + kc + tig;
                bf[nt][0] = Bs[buf][n0];
                bf[nt][1] = Bs[buf][n0 + 4];
            }
#pragma unroll
            for (int mt = 0; mt < 2; mt++)
#pragma unroll
                for (int nt = 0; nt < 4; nt++)
                    mma_tf32(acc[mt][nt], af[mt], bf[nt]);
        }
        if (t + 1 < nk) {
            const int nb = buf ^ 1;
            uint4 ua = make_uint4(f2tf(na0.x * nmm.x), f2tf(na0.y * nmm.y),
                                  f2tf(na0.z * nmm.z), f2tf(na0.w * nmm.w));
            uint4 ub = make_uint4(f2tf(na1.x * nmm.x), f2tf(na1.y * nmm.y),
                                  f2tf(na1.z * nmm.z), f2tf(na1.w * nmm.w));
            uint4 uc = make_uint4(f2tf(nb0.x), f2tf(nb0.y), f2tf(nb0.z), f2tf(nb0.w));
            *(uint4*)&As[nb][rl * SA + fl] = ua;
            *(uint4*)&As[nb][(rl + 64) * SA + fl] = ub;
            *(uint4*)&Bs[nb][rl * SA + fl] = uc;
            __syncthreads();
        }
    }

    // epilogue
    float s0[4] = {}, s1[4] = {}, q0[4] = {}, q1[4] = {};
#pragma unroll
    for (int mt = 0; mt < 2; mt++) {
        int row = i0 + wm * 32 + mt * 16 + gid;
#pragma unroll
        for (int nt = 0; nt < 4; nt++) {
            int col = j0 + wn * 32 + nt * 8 + tig * 2;
            float bia0 = bias[col], bia1 = bias[col + 1];
            float v0 = acc[mt][nt][0] + bia0, v1 = acc[mt][nt][1] + bia1;
            float v2 = acc[mt][nt][2] + bia0, v3 = acc[mt][nt][3] + bia1;
            if (GELU) {
                v0 = 0.5f * v0 * (1.f + erff(v0 * 0.70710678118654752f));
                v1 = 0.5f * v1 * (1.f + erff(v1 * 0.70710678118654752f));
                v2 = 0.5f * v2 * (1.f + erff(v2 * 0.70710678118654752f));
                v3 = 0.5f * v3 * (1.f + erff(v3 * 0.70710678118654752f));
            }
            if (RES) {
                float2 r0 = *(const float2*)(residual + (size_t)row * N + col);
                float2 r1 = *(const float2*)(residual + (size_t)(row + 8) * N + col);
                v0 += r0.x; v1 += r0.y; v2 += r1.x; v3 += r1.y;
            }
            *(float2*)(out + (size_t)row * N + col) = make_float2(v0, v1);
            *(float2*)(out + (size_t)(row + 8) * N + col) = make_float2(v2, v3);
            if (STATS) {
                s0[nt] += v0 + v2; s1[nt] += v1 + v3;
                q0[nt] += v0 * v0 + v2 * v2; q1[nt] += v1 * v1 + v3 * v3;
            }
        }
    }
    if (STATS) {
#pragma unroll
        for (int nt = 0; nt < 4; nt++) {
#pragma unroll
            for (int o = 4; o < 32; o <<= 1) {
                s0[nt] += __shfl_xor_sync(0xffffffffu, s0[nt], o);
                s1[nt] += __shfl_xor_sync(0xffffffffu, s1[nt], o);
                q0[nt] += __shfl_xor_sync(0xffffffffu, q0[nt], o);
                q1[nt] += __shfl_xor_sync(0xffffffffu, q1[nt], o);
            }
            if (gid == 0) {
                int col = j0 + wn * 32 + nt * 8 + tig * 2;
                atomicAdd(&stats[col], s0[nt]);
                atomicAdd(&stats[col + 1], s1[nt]);
                atomicAdd(&stats[CC + col], q0[nt]);
                atomicAdd(&stats[CC + col + 1], q1[nt]);
            }
        }
    }
}

// ---------------- tiled neighborhood attention --------------------------------
struct NattSmem {
    float qs[64 * 32];
    float ks[512 * 34];
    float vs[512 * 34];
    float4 pr[8 * 64];
};
extern __shared__ char natt_raw[];

__global__ void natt_tiled(const float* __restrict__ qkv, float* __restrict__ oatt) {
    NattSmem* S = (NattSmem*)natt_raw;
    const int bx = blockIdx.x;
    const int hy = blockIdx.y;
    const int bd = bx >> 4, bh = (bx >> 2) & 3, bw = bx & 3;
    const int base_d = min(max(4 * bd - 2, 0), 8);
    const int base_h = min(max(4 * bh - 2, 0), 8);
    const int base_w = min(max(4 * bw - 2, 0), 8);
    const int tid = threadIdx.x;

    for (int idx = tid; idx < 64 * 8; idx += 256) {
        int p = idx >> 3, c4 = idx & 7;
        int n = (4 * bd + (p >> 4)) * 256 + (4 * bh + ((p >> 2) & 3)) * 16 + (4 * bw + (p & 3));
        float4 v = *(const float4*)(qkv + (size_t)n * QKV3 + hy * 32 + c4 * 4);
        float* dst = &S->qs[p * 32 + c4 * 4];
        dst[0] = v.x; dst[1] = v.y; dst[2] = v.z; dst[3] = v.w;
    }
    for (int idx = tid; idx < 512 * 8; idx += 256) {
        int r = idx >> 3, c4 = idx & 7;
        int n = (base_d + (r >> 6)) * 256 + (base_h + ((r >> 3) & 7)) * 16 + (base_w + (r & 7));
        const float* src = qkv + (size_t)n * QKV3 + CC + hy * 32 + c4 * 4;
        float4 kv = *(const float4*)src;
        float4 vv = *(const float4*)(src + CC);
        float* kd = &S->ks[r * 34 + c4 * 4];
        kd[0] = kv.x; kd[1] = kv.y; kd[2] = kv.z; kd[3] = kv.w;
        float* vd = &S->vs[r * 34 + c4 * 4];
        vd[0] = vv.x; vd[1] = vv.y; vd[2] = vv.z; vd[3] = vv.w;
    }
    __syncthreads();

    const int w_ = tid >> 5, l = tid & 31;
    float2* prw = (float2*)&S->pr[w_ * 64];
    const float scaleqk = 0.17677669529663689f;

    for (int i = 0; i < 8; i++) {
        int p = w_ * 8 + i;
        int d = 4 * bd + (p >> 4), h = 4 * bh + ((p >> 2) & 3), w = 4 * bw + (p & 3);
        int ld0 = min(max(d - 2, 0), 11) - base_d;
        int lh0 = min(max(h - 2, 0), 11) - base_h;
        int lw0 = min(max(w - 2, 0), 11) - base_w;

        int r[4];
        float s[4];
#pragma unroll
        for (int jj = 0; jj < 4; jj++) {
            int j = l + 32 * jj;
            int jd, jh, jw;
            if (j < 125) { jd = j / 25; jh = (j / 5) % 5; jw = j % 5; }
            else { jd = jh = jw = 0; }
            r[jj] = ((ld0 + jd) * 8 + (lh0 + jh)) * 8 + (lw0 + jw);
            s[jj] = 0.f;
        }
        const float* qrow = &S->qs[p * 32];
#pragma unroll
        for (int c2 = 0; c2 < 16; c2++) {
            float2 q2 = *(const float2*)(qrow + 2 * c2);
#pragma unroll
            for (int jj = 0; jj < 4; jj++) {
                float2 k2 = *(const float2*)(&S->ks[r[jj] * 34 + 2 * c2]);
                s[jj] = fmaf(q2.x, k2.x, fmaf(q2.y, k2.y, s[jj]));
            }
        }
#pragma unroll
        for (int jj = 0; jj < 4; jj++) s[jj] *= scaleqk;
        if (l >= 29) s[3] = -1e30f;

        float mx = fmaxf(fmaxf(s[0], s[1]), fmaxf(s[2], s[3]));
        mx = warp_max(mx);
        float e[4], tot = 0.f;
#pragma unroll
        for (int jj = 0; jj < 4; jj++) { e[jj] = __expf(s[jj] - mx); tot += e[jj]; }
        if (l >= 29) { e[3] = 0.f; tot -= __expf(s[3] - mx); }
        tot = warp_sum(tot);
        float inv = 1.f / tot;
#pragma unroll
        for (int jj = 0; jj < 4; jj++)
            prw[l + 32 * jj] = make_float2(e[jj], __int_as_float(r[jj]));
        __syncwarp();

        float acc = 0.f;
        const float4* pr4 = (const float4*)prw;
#pragma unroll 4
        for (int jb = 0; jb < 64; jb++) {
            float4 t0 = pr4[jb];
            acc = fmaf(t0.x, S->vs[__float_as_int(t0.y) * 34 + l], acc);
            acc = fmaf(t0.z, S->vs[__float_as_int(t0.w) * 34 + l], acc);
        }
        int n = d * 256 + h * 16 + w;
        oatt[(size_t)n * CC + hy * 32 + l] = acc * inv;
        __syncwarp();
    }
}

// ---------------- launch -------------------------------------------------------
extern "C" void kernel_launch(void* const* d_in, const int* in_sizes, int n_in,
                              void* d_out, int out_size) {
    const float* x      = (const float*)d_in[0];
    const float* scale1 = (const float*)d_in[1];
    const float* n1_w1  = (const float*)d_in[2];
    const float* n1_b1  = (const float*)d_in[3];
    const float* n1_w2  = (const float*)d_in[4];
    const float* n1_b2  = (const float*)d_in[5];
    const float* qkv_w  = (const float*)d_in[6];
    const float* qkv_b  = (const float*)d_in[7];
    const float* proj_w = (const float*)d_in[8];
    const float* proj_b = (const float*)d_in[9];
    const float* scale2 = (const float*)d_in[10];
    const float* n2_w1  = (const float*)d_in[11];
    const float* n2_b1  = (const float*)d_in[12];
    const float* n2_w2  = (const float*)d_in[13];
    const float* n2_b2  = (const float*)d_in[14];
    const float* mlp_w1 = (const float*)d_in[15];
    const float* mlp_b1 = (const float*)d_in[16];
    const float* mlp_w2 = (const float*)d_in[17];
    const float* mlp_b2 = (const float*)d_in[18];
    float* out = (float*)d_out;

    float *p_stats, *p_mult, *p_xT, *p_qkv, *p_oatt, *p_x2, *p_m1, *p_y;
    cudaGetSymbolAddress((void**)&p_stats, g_stats);
    cudaGetSymbolAddress((void**)&p_mult,  g_mult);
    cudaGetSymbolAddress((void**)&p_xT,    g_xT);
    cudaGetSymbolAddress((void**)&p_qkv,   g_qkv);
    cudaGetSymbolAddress((void**)&p_oatt,  g_oatt);
    cudaGetSymbolAddress((void**)&p_x2,    g_x2);
    cudaGetSymbolAddress((void**)&p_m1,    g_m1);
    cudaGetSymbolAddress((void**)&p_y,     g_y);

    static bool attr_done = false;
    if (!attr_done) {
        cudaFuncSetAttribute(natt_tiled, cudaFuncAttributeMaxDynamicSharedMemorySize,
                             (int)sizeof(NattSmem));
        attr_done = true;
    }

    // zero stats (used by transpose_stats atomics)
    cudaMemsetAsync(p_stats, 0, 2 * CC * sizeof(float));

    // ---- transpose + norm1 stats ----
    transpose_stats<<<dim3(NN / 32, CC / 32), dim3(32, 8)>>>(x, p_xT, p_stats);
    ada_fused<<<1, 512>>>(p_stats, n1_w1, n1_b1, n1_w2, n1_b2, scale1, p_mult, /*zero=*/1);

    // ---- qkv = (xT * mult1) @ qkv_w^T + b : (4096, 576) ----
    gemm_tc<0, 0, 0><<<dim3(QKV3 / 64, NN / 128), 256>>>(
        NN, QKV3, CC, p_xT, p_mult, qkv_w, qkv_b, nullptr, p_qkv, nullptr);

    // ---- neighborhood attention ----
    natt_tiled<<<dim3(64, NH), 256, sizeof(NattSmem)>>>(p_qkv, p_oatt);

    // ---- x2 = xT + oatt @ proj_w^T + b; fused norm2 stats ----
    gemm_tc<0, 1, 1><<<dim3(CC / 64, NN / 128), 256>>>(
        NN, CC, CC, p_oatt, nullptr, proj_w, proj_b, p_xT, p_x2, p_stats);

    ada_fused<<<1, 512>>>(p_stats, n2_w1, n2_b1, n2_w2, n2_b2, scale2, p_mult, /*zero=*/0);

    // ---- m1 = gelu((x2 * mult2) @ mlp_w1^T + b1) : (4096, 768) ----
    gemm_tc<1, 0, 0><<<dim3(MLPH / 64, NN / 128), 256>>>(
        NN, MLPH, CC, p_x2, p_mult, mlp_w1, mlp_b1, nullptr, p_m1, nullptr);

    // ---- y = x2 + m1 @ mlp_w2^T + b2 : (4096, 192) ----
    gemm_tc<0, 1, 0><<<dim3(CC / 64, NN / 128), 256>>>(
        NN, CC, MLPH, p_m1, nullptr, mlp_w2, mlp_b2, p_x2, p_y, nullptr);

    // ---- out = y^T : (192, 4096) ----
    transpose_k<<<dim3(CC / 32, NN / 32), dim3(32, 8)>>>(p_y, out, NN, CC);
}

// round 10
// speedup vs baseline: 1.0133x; 1.0133x over previous
#include <cuda_runtime.h>
#include <cuda_bf16.h>
#include <cstdint>
#include <math.h>

// Fixed problem shapes
#define CC   192
#define NN   4096           // 16^3
#define HID  384
#define MLPH 768
#define NH   6
#define HD   32
#define QKV3 576

// ---------------- scratch ----------------------------------------------------
__device__ float g_stats[2 * CC];            // [0:192)=sum, [192:384)=sumsq
__device__ float g_mult[CC];
__device__ float g_xT[(size_t)NN * CC];      // x transposed (pos, chan)
__device__ float g_qkv[(size_t)NN * QKV3];   // (pos, 576)
__device__ float g_oatt[(size_t)NN * CC];    // (pos, chan)
__device__ float g_x2[(size_t)NN * CC];      // (pos, chan)
__device__ float g_m1[(size_t)NN * MLPH];    // (pos, 768)
__device__ float g_y[(size_t)NN * CC];       // (pos, chan)

// ---------------- helpers ----------------------------------------------------
__device__ __forceinline__ float warp_sum(float v) {
#pragma unroll
    for (int o = 16; o; o >>= 1) v += __shfl_xor_sync(0xffffffffu, v, o);
    return v;
}
__device__ __forceinline__ float warp_max(float v) {
#pragma unroll
    for (int o = 16; o; o >>= 1) v = fmaxf(v, __shfl_xor_sync(0xffffffffu, v, o));
    return v;
}
__device__ __forceinline__ uint32_t f2tf(float x) {
    uint32_t r;
    asm("cvt.rna.tf32.f32 %0, %1;" : "=r"(r) : "f"(x));
    return r;
}
__device__ __forceinline__ void mma_tf32(float* c, const uint32_t* a, const uint32_t* b) {
    asm volatile(
        "mma.sync.aligned.m16n8k8.row.col.f32.tf32.tf32.f32 "
        "{%0,%1,%2,%3}, {%4,%5,%6,%7}, {%8,%9}, {%0,%1,%2,%3};\n"
        : "+f"(c[0]), "+f"(c[1]), "+f"(c[2]), "+f"(c[3])
        : "r"(a[0]), "r"(a[1]), "r"(a[2]), "r"(a[3]), "r"(b[0]), "r"(b[1]));
}

// ---------------- fused transpose (C,N)->(N,C) + per-channel stats ------------
__global__ void transpose_stats(const float* __restrict__ in, float* __restrict__ outp,
                                float* __restrict__ stats) {
    __shared__ float tle[32][33];
    int c0 = blockIdx.x * 32;  // position block
    int r0 = blockIdx.y * 32;  // channel block
    int tx = threadIdx.x, ty = threadIdx.y;
#pragma unroll
    for (int u = 0; u < 32; u += 8)
        tle[ty + u][tx] = in[(size_t)(r0 + ty + u) * NN + c0 + tx];
    __syncthreads();
#pragma unroll
    for (int u = 0; u < 32; u += 8)
        outp[(size_t)(c0 + ty + u) * CC + r0 + tx] = tle[tx][ty + u];
    if (ty == 0) {
        float s = 0.f, s2 = 0.f;
#pragma unroll
        for (int p = 0; p < 32; p++) { float v = tle[tx][p]; s += v; s2 += v * v; }
        atomicAdd(&stats[r0 + tx], s);
        atomicAdd(&stats[CC + r0 + tx], s2);
    }
}

// ---------------- plain transpose (R,C) -> (C,R) ------------------------------
__global__ void transpose_k(const float* __restrict__ in, float* __restrict__ out,
                            int R, int C) {
    __shared__ float t[32][33];
    int c0 = blockIdx.x * 32, r0 = blockIdx.y * 32;
    int tx = threadIdx.x, ty = threadIdx.y;
#pragma unroll
    for (int u = 0; u < 32; u += 8)
        t[ty + u][tx] = in[(size_t)(r0 + ty + u) * C + c0 + tx];
    __syncthreads();
#pragma unroll
    for (int u = 0; u < 32; u += 8)
        out[(size_t)(c0 + ty + u) * R + r0 + tx] = t[tx][ty + u];
}

// ---------------- fused ada gating (hidden + mult + optional zero) ------------
__global__ void __launch_bounds__(512) ada_fused(
    float* __restrict__ stats,
    const float* __restrict__ w1, const float* __restrict__ b1,
    const float* __restrict__ w2, const float* __restrict__ b2,
    const float* __restrict__ scale, float* __restrict__ mult, int zero) {
    __shared__ float mean_s[CC];
    __shared__ float h_s[HID];
    int tid = threadIdx.x, wid = tid >> 5, lane = tid & 31;
    if (tid < CC) mean_s[tid] = stats[tid] * (1.f / NN);
    __syncthreads();
    for (int r = wid; r < HID; r += 16) {
        const float* wr = w1 + (size_t)r * CC;
        float a = 0.f;
#pragma unroll
        for (int c = lane; c < CC; c += 32) a += mean_s[c] * wr[c];
        a = warp_sum(a);
        if (lane == 0) h_s[r] = fmaxf(a + b1[r], 0.f);
    }
    __syncthreads();
    for (int r = wid; r < CC; r += 16) {
        const float* wr = w2 + (size_t)r * HID;
        float a = 0.f;
#pragma unroll
        for (int i = lane; i < HID; i += 32) a += h_s[i] * wr[i];
        a = warp_sum(a);
        if (lane == 0) {
            float g = 1.f / (1.f + __expf(-(a + b2[r])));
            mult[r] = scale[r] * g * rsqrtf(stats[CC + r] * (1.f / NN) + 1e-6f);
        }
    }
    if (zero) {
        __syncthreads();
        if (tid < 2 * CC) stats[tid] = 0.f;
    }
}

// ---------------- tf32 tensor-core GEMM ---------------------------------------
// out(M,N) = epi( A(M,K)*diag(Amult) @ B(N,K)^T + bias[col] )  [+residual] [stats]
// CTA tile 128x64x16, 8 warps of 32x32, mma.m16n8k8.tf32.
#define SA 20   // smem row stride (16 + 4 pad) -> conflict-free fragment loads

template <int GELU, int RES, int STATS>
__global__ void __launch_bounds__(256) gemm_tc(
    int M, int N, int K,
    const float* __restrict__ A, const float* __restrict__ Amult,
    const float* __restrict__ B,
    const float* __restrict__ bias,
    const float* __restrict__ residual,
    float* __restrict__ out,
    float* __restrict__ stats) {
    __shared__ uint32_t As[2][128 * SA];
    __shared__ uint32_t Bs[2][64 * SA];

    const int i0 = blockIdx.y * 128, j0 = blockIdx.x * 64;
    const int tid = threadIdx.x;
    const int rl = tid >> 2, fl = (tid & 3) * 4;
    const int warp = tid >> 5, lane = tid & 31;
    const int wm = warp >> 1, wn = warp & 1;
    const int gid = lane >> 2, tig = lane & 3;

    const float* Ap = A + (size_t)(i0 + rl) * K + fl;
    const float* Aq = A + (size_t)(i0 + rl + 64) * K + fl;
    const float* Bp = B + (size_t)(j0 + rl) * K + fl;

    // preload tile 0
    {
        float4 a0 = *(const float4*)Ap;
        float4 a1 = *(const float4*)Aq;
        float4 b0 = *(const float4*)Bp;
        float4 mm = Amult ? *(const float4*)(Amult + fl) : make_float4(1.f, 1.f, 1.f, 1.f);
        uint4 ua = make_uint4(f2tf(a0.x * mm.x), f2tf(a0.y * mm.y),
                              f2tf(a0.z * mm.z), f2tf(a0.w * mm.w));
        uint4 ub = make_uint4(f2tf(a1.x * mm.x), f2tf(a1.y * mm.y),
                              f2tf(a1.z * mm.z), f2tf(a1.w * mm.w));
        uint4 uc = make_uint4(f2tf(b0.x), f2tf(b0.y), f2tf(b0.z), f2tf(b0.w));
        *(uint4*)&As[0][rl * SA + fl] = ua;
        *(uint4*)&As[0][(rl + 64) * SA + fl] = ub;
        *(uint4*)&Bs[0][rl * SA + fl] = uc;
    }
    __syncthreads();

    float acc[2][4][4] = {};
    const int nk = K / 16;

    for (int t = 0; t < nk; t++) {
        const int buf = t & 1;
        float4 na0, na1, nb0, nmm;
        if (t + 1 < nk) {
            int off = (t + 1) * 16;
            na0 = *(const float4*)(Ap + off);
            na1 = *(const float4*)(Aq + off);
            nb0 = *(const float4*)(Bp + off);
            nmm = Amult ? *(const float4*)(Amult + off + fl) : make_float4(1.f, 1.f, 1.f, 1.f);
        }
#pragma unroll
        for (int kc = 0; kc < 16; kc += 8) {
            uint32_t af[2][4], bf[4][2];
#pragma unroll
            for (int mt = 0; mt < 2; mt++) {
                int r0 = (wm * 32 + mt * 16 + gid) * SA + kc + tig;
                af[mt][0] = As[buf][r0];
                af[mt][1] = As[buf][r0 + 8 * SA];
                af[mt][2] = As[buf][r0 + 4];
                af[mt][3] = As[buf][r0 + 8 * SA + 4];
            }
#pragma unroll
            for (int nt = 0; nt < 4; nt++) {
                int n0 = (wn * 32 + nt * 8 + gid) * SA + kc + tig;
                bf[nt][0] = Bs[buf][n0];
                bf[nt][1] = Bs[buf][n0 + 4];
            }
#pragma unroll
            for (int mt = 0; mt < 2; mt++)
#pragma unroll
                for (int nt = 0; nt < 4; nt++)
                    mma_tf32(acc[mt][nt], af[mt], bf[nt]);
        }
        if (t + 1 < nk) {
            const int nb = buf ^ 1;
            uint4 ua = make_uint4(f2tf(na0.x * nmm.x), f2tf(na0.y * nmm.y),
                                  f2tf(na0.z * nmm.z), f2tf(na0.w * nmm.w));
            uint4 ub = make_uint4(f2tf(na1.x * nmm.x), f2tf(na1.y * nmm.y),
                                  f2tf(na1.z * nmm.z), f2tf(na1.w * nmm.w));
            uint4 uc = make_uint4(f2tf(nb0.x), f2tf(nb0.y), f2tf(nb0.z), f2tf(nb0.w));
            *(uint4*)&As[nb][rl * SA + fl] = ua;
            *(uint4*)&As[nb][(rl + 64) * SA + fl] = ub;
            *(uint4*)&Bs[nb][rl * SA + fl] = uc;
            __syncthreads();
        }
    }

    // epilogue
    float s0[4] = {}, s1[4] = {}, q0[4] = {}, q1[4] = {};
#pragma unroll
    for (int mt = 0; mt < 2; mt++) {
        int row = i0 + wm * 32 + mt * 16 + gid;
#pragma unroll
        for (int nt = 0; nt < 4; nt++) {
            int col = j0 + wn * 32 + nt * 8 + tig * 2;
            float bia0 = bias[col], bia1 = bias[col + 1];
            float v0 = acc[mt][nt][0] + bia0, v1 = acc[mt][nt][1] + bia1;
            float v2 = acc[mt][nt][2] + bia0, v3 = acc[mt][nt][3] + bia1;
            if (GELU) {
                v0 = 0.5f * v0 * (1.f + erff(v0 * 0.70710678118654752f));
                v1 = 0.5f * v1 * (1.f + erff(v1 * 0.70710678118654752f));
                v2 = 0.5f * v2 * (1.f + erff(v2 * 0.70710678118654752f));
                v3 = 0.5f * v3 * (1.f + erff(v3 * 0.70710678118654752f));
            }
            if (RES) {
                float2 r0 = *(const float2*)(residual + (size_t)row * N + col);
                float2 r1 = *(const float2*)(residual + (size_t)(row + 8) * N + col);
                v0 += r0.x; v1 += r0.y; v2 += r1.x; v3 += r1.y;
            }
            *(float2*)(out + (size_t)row * N + col) = make_float2(v0, v1);
            *(float2*)(out + (size_t)(row + 8) * N + col) = make_float2(v2, v3);
            if (STATS) {
                s0[nt] += v0 + v2; s1[nt] += v1 + v3;
                q0[nt] += v0 * v0 + v2 * v2; q1[nt] += v1 * v1 + v3 * v3;
            }
        }
    }
    if (STATS) {
#pragma unroll
        for (int nt = 0; nt < 4; nt++) {
#pragma unroll
            for (int o = 4; o < 32; o <<= 1) {
                s0[nt] += __shfl_xor_sync(0xffffffffu, s0[nt], o);
                s1[nt] += __shfl_xor_sync(0xffffffffu, s1[nt], o);
                q0[nt] += __shfl_xor_sync(0xffffffffu, q0[nt], o);
                q1[nt] += __shfl_xor_sync(0xffffffffu, q1[nt], o);
            }
            if (gid == 0) {
                int col = j0 + wn * 32 + nt * 8 + tig * 2;
                atomicAdd(&stats[col], s0[nt]);
                atomicAdd(&stats[col + 1], s1[nt]);
                atomicAdd(&stats[CC + col], q0[nt]);
                atomicAdd(&stats[CC + col + 1], q1[nt]);
            }
        }
    }
}

// ---------------- tiled neighborhood attention --------------------------------
struct NattSmem {
    float qs[64 * 32];
    float ks[512 * 34];
    float vs[512 * 34];
    float4 pr[8 * 64];
};
extern __shared__ char natt_raw[];

__global__ void natt_tiled(const float* __restrict__ qkv, float* __restrict__ oatt) {
    NattSmem* S = (NattSmem*)natt_raw;
    const int bx = blockIdx.x;
    const int hy = blockIdx.y;
    const int bd = bx >> 4, bh = (bx >> 2) & 3, bw = bx & 3;
    const int base_d = min(max(4 * bd - 2, 0), 8);
    const int base_h = min(max(4 * bh - 2, 0), 8);
    const int base_w = min(max(4 * bw - 2, 0), 8);
    const int tid = threadIdx.x;

    for (int idx = tid; idx < 64 * 8; idx += 256) {
        int p = idx >> 3, c4 = idx & 7;
        int n = (4 * bd + (p >> 4)) * 256 + (4 * bh + ((p >> 2) & 3)) * 16 + (4 * bw + (p & 3));
        float4 v = *(const float4*)(qkv + (size_t)n * QKV3 + hy * 32 + c4 * 4);
        float* dst = &S->qs[p * 32 + c4 * 4];
        dst[0] = v.x; dst[1] = v.y; dst[2] = v.z; dst[3] = v.w;
    }
    for (int idx = tid; idx < 512 * 8; idx += 256) {
        int r = idx >> 3, c4 = idx & 7;
        int n = (base_d + (r >> 6)) * 256 + (base_h + ((r >> 3) & 7)) * 16 + (base_w + (r & 7));
        const float* src = qkv + (size_t)n * QKV3 + CC + hy * 32 + c4 * 4;
        float4 kv = *(const float4*)src;
        float4 vv = *(const float4*)(src + CC);
        float* kd = &S->ks[r * 34 + c4 * 4];
        kd[0] = kv.x; kd[1] = kv.y; kd[2] = kv.z; kd[3] = kv.w;
        float* vd = &S->vs[r * 34 + c4 * 4];
        vd[0] = vv.x; vd[1] = vv.y; vd[2] = vv.z; vd[3] = vv.w;
    }
    __syncthreads();

    const int w_ = tid >> 5, l = tid & 31;
    float2* prw = (float2*)&S->pr[w_ * 64];
    const float scaleqk = 0.17677669529663689f;

    for (int i = 0; i < 8; i++) {
        int p = w_ * 8 + i;
        int d = 4 * bd + (p >> 4), h = 4 * bh + ((p >> 2) & 3), w = 4 * bw + (p & 3);
        int ld0 = min(max(d - 2, 0), 11) - base_d;
        int lh0 = min(max(h - 2, 0), 11) - base_h;
        int lw0 = min(max(w - 2, 0), 11) - base_w;

        int r[4];
        float s[4];
#pragma unroll
        for (int jj = 0; jj < 4; jj++) {
            int j = l + 32 * jj;
            int jd, jh, jw;
            if (j < 125) { jd = j / 25; jh = (j / 5) % 5; jw = j % 5; }
            else { jd = jh = jw = 0; }
            r[jj] = ((ld0 + jd) * 8 + (lh0 + jh)) * 8 + (lw0 + jw);
            s[jj] = 0.f;
        }
        const float* qrow = &S->qs[p * 32];
#pragma unroll
        for (int c2 = 0; c2 < 16; c2++) {
            float2 q2 = *(const float2*)(qrow + 2 * c2);
#pragma unroll
            for (int jj = 0; jj < 4; jj++) {
                float2 k2 = *(const float2*)(&S->ks[r[jj] * 34 + 2 * c2]);
                s[jj] = fmaf(q2.x, k2.x, fmaf(q2.y, k2.y, s[jj]));
            }
        }
#pragma unroll
        for (int jj = 0; jj < 4; jj++) s[jj] *= scaleqk;
        if (l >= 29) s[3] = -1e30f;

        float mx = fmaxf(fmaxf(s[0], s[1]), fmaxf(s[2], s[3]));
        mx = warp_max(mx);
        float e[4], tot = 0.f;
#pragma unroll
        for (int jj = 0; jj < 4; jj++) { e[jj] = __expf(s[jj] - mx); tot += e[jj]; }
        if (l >= 29) { e[3] = 0.f; tot -= __expf(s[3] - mx); }
        tot = warp_sum(tot);
        float inv = 1.f / tot;
#pragma unroll
        for (int jj = 0; jj < 4; jj++)
            prw[l + 32 * jj] = make_float2(e[jj], __int_as_float(r[jj]));
        __syncwarp();

        float acc = 0.f;
        const float4* pr4 = (const float4*)prw;
#pragma unroll 4
        for (int jb = 0; jb < 64; jb++) {
            float4 t0 = pr4[jb];
            acc = fmaf(t0.x, S->vs[__float_as_int(t0.y) * 34 + l], acc);
            acc = fmaf(t0.z, S->vs[__float_as_int(t0.w) * 34 + l], acc);
        }
        int n = d * 256 + h * 16 + w;
        oatt[(size_t)n * CC + hy * 32 + l] = acc * inv;
        __syncwarp();
    }
}

// ---------------- launch -------------------------------------------------------
extern "C" void kernel_launch(void* const* d_in, const int* in_sizes, int n_in,
                              void* d_out, int out_size) {
    const float* x      = (const float*)d_in[0];
    const float* scale1 = (const float*)d_in[1];
    const float* n1_w1  = (const float*)d_in[2];
    const float* n1_b1  = (const float*)d_in[3];
    const float* n1_w2  = (const float*)d_in[4];
    const float* n1_b2  = (const float*)d_in[5];
    const float* qkv_w  = (const float*)d_in[6];
    const float* qkv_b  = (const float*)d_in[7];
    const float* proj_w = (const float*)d_in[8];
    const float* proj_b = (const float*)d_in[9];
    const float* scale2 = (const float*)d_in[10];
    const float* n2_w1  = (const float*)d_in[11];
    const float* n2_b1  = (const float*)d_in[12];
    const float* n2_w2  = (const float*)d_in[13];
    const float* n2_b2  = (const float*)d_in[14];
    const float* mlp_w1 = (const float*)d_in[15];
    const float* mlp_b1 = (const float*)d_in[16];
    const float* mlp_w2 = (const float*)d_in[17];
    const float* mlp_b2 = (const float*)d_in[18];
    float* out = (float*)d_out;

    float *p_stats, *p_mult, *p_xT, *p_qkv, *p_oatt, *p_x2, *p_m1, *p_y;
    cudaGetSymbolAddress((void**)&p_stats, g_stats);
    cudaGetSymbolAddress((void**)&p_mult,  g_mult);
    cudaGetSymbolAddress((void**)&p_xT,    g_xT);
    cudaGetSymbolAddress((void**)&p_qkv,   g_qkv);
    cudaGetSymbolAddress((void**)&p_oatt,  g_oatt);
    cudaGetSymbolAddress((void**)&p_x2,    g_x2);
    cudaGetSymbolAddress((void**)&p_m1,    g_m1);
    cudaGetSymbolAddress((void**)&p_y,     g_y);

    static bool attr_done = false;
    if (!attr_done) {
        cudaFuncSetAttribute(natt_tiled, cudaFuncAttributeMaxDynamicSharedMemorySize,
                             (int)sizeof(NattSmem));
        attr_done = true;
    }

    // zero stats (used by transpose_stats atomics)
    cudaMemsetAsync(p_stats, 0, 2 * CC * sizeof(float));

    // ---- transpose + norm1 stats ----
    transpose_stats<<<dim3(NN / 32, CC / 32), dim3(32, 8)>>>(x, p_xT, p_stats);
    ada_fused<<<1, 512>>>(p_stats, n1_w1, n1_b1, n1_w2, n1_b2, scale1, p_mult, /*zero=*/1);

    // ---- qkv = (xT * mult1) @ qkv_w^T + b : (4096, 576) ----
    gemm_tc<0, 0, 0><<<dim3(QKV3 / 64, NN / 128), 256>>>(
        NN, QKV3, CC, p_xT, p_mult, qkv_w, qkv_b, nullptr, p_qkv, nullptr);

    // ---- neighborhood attention ----
    natt_tiled<<<dim3(64, NH), 256, sizeof(NattSmem)>>>(p_qkv, p_oatt);

    // ---- x2 = xT + oatt @ proj_w^T + b; fused norm2 stats ----
    gemm_tc<0, 1, 1><<<dim3(CC / 64, NN / 128), 256>>>(
        NN, CC, CC, p_oatt, nullptr, proj_w, proj_b, p_xT, p_x2, p_stats);

    ada_fused<<<1, 512>>>(p_stats, n2_w1, n2_b1, n2_w2, n2_b2, scale2, p_mult, /*zero=*/0);

    // ---- m1 = gelu((x2 * mult2) @ mlp_w1^T + b1) : (4096, 768) ----
    gemm_tc<1, 0, 0><<<dim3(MLPH / 64, NN / 128), 256>>>(
        NN, MLPH, CC, p_x2, p_mult, mlp_w1, mlp_b1, nullptr, p_m1, nullptr);

    // ---- y = x2 + m1 @ mlp_w2^T + b2 : (4096, 192) ----
    gemm_tc<0, 1, 0><<<dim3(CC / 64, NN / 128), 256>>>(
        NN, CC, MLPH, p_m1, nullptr, mlp_w2, mlp_b2, p_x2, p_y, nullptr);

    // ---- out = y^T : (192, 4096) ----
    transpose_k<<<dim3(CC / 32, NN / 32), dim3(32, 8)>>>(p_y, out, NN, CC);
}